// round 3
// baseline (speedup 1.0000x reference)
#include <cuda_runtime.h>
#include <cuda_bf16.h>
#include <mma.h>
#include <cstdint>

using namespace nvcuda;

// Problem dims
#define BB   64
#define SS   512
#define NHH  4
#define DD   256
#define HH   256
#define MROWS (BB*SS*NHH)   // 131072

// ---------------- device scratch (static, allocation-free) ----------------
__device__ float g_kxW[(size_t)MROWS * 256];   // x @ (Wk@Wcomb)            (no bias)
__device__ float g_xW1[(size_t)MROWS * 256];   // x @ W1_top                (no bias)
__device__ float g_kscore[MROWS];
__device__ float g_Wcomb[256 * 256];           // Wproj @ W1_bot
__device__ float g_Wbig[256 * 512];            // [Wk@Wcomb | W1_top]  (K=256 rows, N=512)
__device__ float g_bias[512];                  // [bk@Wcomb | b1 + bproj@W1bot]
__device__ float g_vq[256];                    // Wq @ w2
__device__ float g_wk1[256];                   // Wk @ w1
__device__ float g_w2v[256];                   // W2 @ vq
__device__ float g_scalars[4];
__device__ float g_h1[BB * NHH * 256];
__device__ float g_hidden[BB * NHH * 256];
// bf16 split planes, row-major
__device__ __nv_bfloat16 g_Ahi[(size_t)MROWS * 256];
__device__ __nv_bfloat16 g_Alo[(size_t)MROWS * 256];
__device__ __nv_bfloat16 g_Bhi[256 * 512];
__device__ __nv_bfloat16 g_Blo[256 * 512];

// ---------------- helpers ----------------
__device__ __forceinline__ uint32_t smem_u32(const void* p) {
    uint32_t a;
    asm("{ .reg .u64 t; cvta.to.shared.u64 t, %1; cvt.u32.u64 %0, t; }" : "=r"(a) : "l"(p));
    return a;
}
__device__ __forceinline__ void cpa16(void* s, const void* g) {
    uint32_t sa = smem_u32(s);
    asm volatile("cp.async.cg.shared.global [%0], [%1], 16;" :: "r"(sa), "l"(g));
}
__device__ __forceinline__ void cp16ca(float* s, const float* g) {
    uint32_t sa = smem_u32(s);
    asm volatile("cp.async.ca.shared.global [%0], [%1], 16;" :: "r"(sa), "l"(g));
}

// ---------------- small setup kernels ----------------
__global__ void k_setup1(const float* __restrict__ Wk, const float* __restrict__ bk,
                         const float* __restrict__ Wq, const float* __restrict__ bq,
                         const float* __restrict__ w_mlp) {
    __shared__ float sw1[256], sw2[256];
    int tid = threadIdx.x;
    sw1[tid] = w_mlp[tid];
    sw2[tid] = w_mlp[256 + tid];
    __syncthreads();
    float vq = 0.f, wk1 = 0.f;
    for (int h = 0; h < 256; h++) {
        vq  += Wq[tid * 256 + h] * sw2[h];
        wk1 += Wk[tid * 256 + h] * sw1[h];
    }
    g_vq[tid] = vq;
    g_wk1[tid] = wk1;
    if (tid == 0) {
        float cq = 0.f, ck1 = 0.f;
        for (int h = 0; h < 256; h++) { cq += bq[h] * sw2[h]; ck1 += bk[h] * sw1[h]; }
        g_scalars[0] = cq;
        g_scalars[1] = ck1;
    }
}

__global__ void k_wcomb(const float* __restrict__ Wproj, const float* __restrict__ W1) {
    __shared__ float sp[256];
    int h = blockIdx.x, tid = threadIdx.x;
    sp[tid] = Wproj[h * 256 + tid];
    __syncthreads();
    float acc = 0.f;
    for (int hp = 0; hp < 256; hp++)
        acc += sp[hp] * W1[(256 + hp) * 256 + tid];
    g_Wcomb[h * 256 + tid] = acc;
}

__global__ void k_wkc(const float* __restrict__ Wk, const float* __restrict__ W1,
                      const float* __restrict__ bk, const float* __restrict__ b1,
                      const float* __restrict__ bproj, const float* __restrict__ W2,
                      const float* __restrict__ b2) {
    int tid = threadIdx.x;
    if (blockIdx.x < 256) {
        int d = blockIdx.x;
        __shared__ float s[256];
        s[tid] = Wk[d * 256 + tid];
        __syncthreads();
        float acc = 0.f;
        for (int h = 0; h < 256; h++) acc += s[h] * g_Wcomb[h * 256 + tid];
        g_Wbig[d * 512 + tid]       = acc;
        g_Wbig[d * 512 + 256 + tid] = W1[d * 256 + tid];
    } else {
        float a = 0.f, bb = 0.f, w = 0.f;
        for (int h = 0; h < 256; h++) a  += bk[h]    * g_Wcomb[h * 256 + tid];
        for (int h = 0; h < 256; h++) bb += bproj[h] * W1[(256 + h) * 256 + tid];
        for (int h = 0; h < 256; h++) w  += W2[tid * 256 + h] * g_vq[h];
        g_bias[tid]       = a;
        g_bias[256 + tid] = b1[tid] + bb;
        g_w2v[tid] = w;
        if (tid == 0) {
            float c2 = 0.f;
            for (int h = 0; h < 256; h++) c2 += b2[h] * g_vq[h];
            g_scalars[2] = c2 + g_scalars[0];
        }
    }
}

// ---------------- conversion: x -> bf16 hi/lo planes (+ fused kscore) ----------
__global__ void __launch_bounds__(256) k_convA(const float* __restrict__ X) {
    int idx = blockIdx.x * 256 + threadIdx.x;   // one 8-element chunk per thread
    size_t row = (size_t)idx >> 5;              // 32 chunks of 8 per row of 256
    int q = idx & 31;
    const float* src = X + row * 256 + q * 8;
    float v[8];
    *(float4*)(v)     = *(const float4*)(src);
    *(float4*)(v + 4) = *(const float4*)(src + 4);
    float wkv[8];
    *(float4*)(wkv)     = *(const float4*)(g_wk1 + q * 8);
    *(float4*)(wkv + 4) = *(const float4*)(g_wk1 + q * 8 + 4);
    __nv_bfloat16 hi[8], lo[8];
    float dot = 0.f;
#pragma unroll
    for (int j = 0; j < 8; j++) {
        hi[j] = __float2bfloat16(v[j]);
        lo[j] = __float2bfloat16(v[j] - __bfloat162float(hi[j]));
        dot += v[j] * wkv[j];
    }
    *(uint4*)(g_Ahi + row * 256 + q * 8) = *(uint4*)hi;
    *(uint4*)(g_Alo + row * 256 + q * 8) = *(uint4*)lo;
#pragma unroll
    for (int off = 16; off; off >>= 1) dot += __shfl_down_sync(0xFFFFFFFFu, dot, off);
    if ((threadIdx.x & 31) == 0) g_kscore[row] = dot + g_scalars[1];
}

__global__ void k_convB() {
    int idx = blockIdx.x * 256 + threadIdx.x;   // 256*512 = 131072 elems
    float w = g_Wbig[idx];
    __nv_bfloat16 hi = __float2bfloat16(w);
    __nv_bfloat16 lo = __float2bfloat16(w - __bfloat162float(hi));
    g_Bhi[idx] = hi;
    g_Blo[idx] = lo;
}

// ---------------- wmma GEMM: C(131072x512) = X @ Wbig (split bf16, 3 products) ----
// CTA tile M=128 N=128, K chunks of 32 double-buffered. 8 warps: 4(m) x 2(n).
#define WSM_STAGE 32768   // Ahi 8K | Alo 8K | Bhi 8K | Blo 8K
#define WSM_TOTAL (2 * WSM_STAGE)

__device__ __forceinline__ void wmma_load_stage(char* smem, int buf, int rb, int nb,
                                                int kc, int tid) {
    char* base = smem + buf * WSM_STAGE;
#pragma unroll
    for (int t = tid; t < 512; t += 256) {
        int row = t >> 2, ch = t & 3;
        size_t goff = ((size_t)(rb * 128 + row)) * 256 + kc * 32 + ch * 8;
        int soff = (row * 32 + ch * 8) * 2;
        cpa16(base + soff,        g_Ahi + goff);
        cpa16(base + 8192 + soff, g_Alo + goff);
    }
#pragma unroll
    for (int t = tid; t < 512; t += 256) {
        int kr = t >> 4, ch = t & 15;
        size_t goff = ((size_t)(kc * 32 + kr)) * 512 + nb * 128 + ch * 8;
        int soff = (kr * 128 + ch * 8) * 2;
        cpa16(base + 16384 + soff, g_Bhi + goff);
        cpa16(base + 24576 + soff, g_Blo + goff);
    }
}

__global__ void __launch_bounds__(256) k_wmma() {
    extern __shared__ __align__(128) char smem[];
    const int nb = blockIdx.x;   // 0..3  (N column block of 128)
    const int rb = blockIdx.y;   // 0..1023
    const int tid = threadIdx.x;
    const int w = tid >> 5;
    const int warp_m = w & 3, warp_n = w >> 2;

    wmma::fragment<wmma::accumulator, 16, 16, 16, float> acc[2][4];
#pragma unroll
    for (int i = 0; i < 2; i++)
#pragma unroll
        for (int j = 0; j < 4; j++) wmma::fill_fragment(acc[i][j], 0.f);

    wmma_load_stage(smem, 0, rb, nb, 0, tid);
    asm volatile("cp.async.commit_group;" ::: "memory");

    for (int kc = 0; kc < 8; kc++) {
        const int buf = kc & 1;
        if (kc + 1 < 8) {
            wmma_load_stage(smem, buf ^ 1, rb, nb, kc + 1, tid);
            asm volatile("cp.async.commit_group;" ::: "memory");
            asm volatile("cp.async.wait_group 1;" ::: "memory");
        } else {
            asm volatile("cp.async.wait_group 0;" ::: "memory");
        }
        __syncthreads();

        const __nv_bfloat16* sAh = (const __nv_bfloat16*)(smem + buf * WSM_STAGE);
        const __nv_bfloat16* sAl = sAh + 4096;
        const __nv_bfloat16* sBh = sAh + 8192;
        const __nv_bfloat16* sBl = sAh + 12288;

#pragma unroll
        for (int kk = 0; kk < 32; kk += 16) {
            wmma::fragment<wmma::matrix_a, 16, 16, 16, __nv_bfloat16, wmma::row_major> fa_hi[2], fa_lo[2];
            wmma::fragment<wmma::matrix_b, 16, 16, 16, __nv_bfloat16, wmma::row_major> fb_hi[4], fb_lo[4];
#pragma unroll
            for (int i = 0; i < 2; i++) {
                int m = warp_m * 32 + i * 16;
                wmma::load_matrix_sync(fa_hi[i], sAh + m * 32 + kk, 32);
                wmma::load_matrix_sync(fa_lo[i], sAl + m * 32 + kk, 32);
            }
#pragma unroll
            for (int j = 0; j < 4; j++) {
                int n = warp_n * 64 + j * 16;
                wmma::load_matrix_sync(fb_hi[j], sBh + kk * 128 + n, 128);
                wmma::load_matrix_sync(fb_lo[j], sBl + kk * 128 + n, 128);
            }
#pragma unroll
            for (int i = 0; i < 2; i++)
#pragma unroll
                for (int j = 0; j < 4; j++) {
                    wmma::mma_sync(acc[i][j], fa_hi[i], fb_hi[j], acc[i][j]);
                    wmma::mma_sync(acc[i][j], fa_hi[i], fb_lo[j], acc[i][j]);
                    wmma::mma_sync(acc[i][j], fa_lo[i], fb_hi[j], acc[i][j]);
                }
        }
        __syncthreads();
    }

    float* Cout = (nb < 2) ? g_kxW : g_xW1;
    const int colbase = (nb & 1) * 128;
#pragma unroll
    for (int i = 0; i < 2; i++) {
        size_t row = (size_t)rb * 128 + warp_m * 32 + i * 16;
#pragma unroll
        for (int j = 0; j < 4; j++) {
            int col = colbase + warp_n * 64 + j * 16;
            wmma::store_matrix_sync(Cout + row * 256 + col, acc[i][j], 256, wmma::mem_row_major);
        }
    }
}

// ---------------- recurrent scan: one CTA per batch element ----------------
__global__ void __launch_bounds__(256) k_recurrent() {
    const int b = blockIdx.x;
    const int tid = threadIdx.x;
    const int lane = tid & 31, wid = tid >> 5;
    __shared__ __align__(16) float sk[2][1024];
    __shared__ __align__(16) float sx[2][1024];
    __shared__ __align__(16) float sks[2][4];
    __shared__ float qs[4];
    __shared__ float ps[16];
    __shared__ float wp[8][4];

    const float w2vh = g_w2v[tid];
    const float c2 = g_scalars[2];
    const float bk_ = g_bias[tid];        // column bias for kx path
    const float bx_ = g_bias[256 + tid];  // column bias for xW1 path
    if (tid < 4) qs[tid] = g_scalars[0];

    {
        size_t base0 = ((size_t)b * 512 + 0) * 4 * 256;
        cp16ca(&sk[0][tid * 4], g_kxW + base0 + (size_t)tid * 4);
        cp16ca(&sx[0][tid * 4], g_xW1 + base0 + (size_t)tid * 4);
        if (tid == 0) cp16ca(sks[0], g_kscore + ((size_t)b * 512 + 0) * 4);
        asm volatile("cp.async.commit_group;" ::: "memory");
        size_t base1 = ((size_t)b * 512 + 1) * 4 * 256;
        cp16ca(&sk[1][tid * 4], g_kxW + base1 + (size_t)tid * 4);
        cp16ca(&sx[1][tid * 4], g_xW1 + base1 + (size_t)tid * 4);
        if (tid == 0) cp16ca(sks[1], g_kscore + ((size_t)b * 512 + 1) * 4);
        asm volatile("cp.async.commit_group;" ::: "memory");
    }
    __syncthreads();

    for (int t = 0; t < 512; t++) {
        const int buf = t & 1;
        asm volatile("cp.async.wait_group 1;" ::: "memory");
        __syncthreads();

        if (tid < 16) {
            int i = tid >> 2;
            float s = tanhf(qs[i] + sks[buf][tid & 3]);
            float m = fmaxf(s, __shfl_xor_sync(0xFFFFu, s, 1));
            m = fmaxf(m, __shfl_xor_sync(0xFFFFu, m, 2));
            float e = __expf(s - m);
            float sum = e + __shfl_xor_sync(0xFFFFu, e, 1);
            sum += __shfl_xor_sync(0xFFFFu, sum, 2);
            ps[tid] = e / sum;
        }
        __syncthreads();

        const float k0 = sk[buf][tid] + bk_, k1 = sk[buf][256 + tid] + bk_,
                    k2 = sk[buf][512 + tid] + bk_, k3 = sk[buf][768 + tid] + bk_;
        float a0, a1, a2, a3;
        {
            float v = sx[buf][tid] + bx_ + ps[0] * k0 + ps[1] * k1 + ps[2] * k2 + ps[3] * k3;
            float h = fmaxf(v, 0.f);
            if (t == 511) g_h1[(b * 4 + 0) * 256 + tid] = h;
            a0 = h * w2vh;
        }
        {
            float v = sx[buf][256 + tid] + bx_ + ps[4] * k0 + ps[5] * k1 + ps[6] * k2 + ps[7] * k3;
            float h = fmaxf(v, 0.f);
            if (t == 511) g_h1[(b * 4 + 1) * 256 + tid] = h;
            a1 = h * w2vh;
        }
        {
            float v = sx[buf][512 + tid] + bx_ + ps[8] * k0 + ps[9] * k1 + ps[10] * k2 + ps[11] * k3;
            float h = fmaxf(v, 0.f);
            if (t == 511) g_h1[(b * 4 + 2) * 256 + tid] = h;
            a2 = h * w2vh;
        }
        {
            float v = sx[buf][768 + tid] + bx_ + ps[12] * k0 + ps[13] * k1 + ps[14] * k2 + ps[15] * k3;
            float h = fmaxf(v, 0.f);
            if (t == 511) g_h1[(b * 4 + 3) * 256 + tid] = h;
            a3 = h * w2vh;
        }
#pragma unroll
        for (int off = 16; off; off >>= 1) {
            a0 += __shfl_down_sync(0xFFFFFFFFu, a0, off);
            a1 += __shfl_down_sync(0xFFFFFFFFu, a1, off);
            a2 += __shfl_down_sync(0xFFFFFFFFu, a2, off);
            a3 += __shfl_down_sync(0xFFFFFFFFu, a3, off);
        }
        if (lane == 0) { wp[wid][0] = a0; wp[wid][1] = a1; wp[wid][2] = a2; wp[wid][3] = a3; }
        __syncthreads();

        if (t + 2 < 512) {
            size_t base = ((size_t)b * 512 + t + 2) * 4 * 256;
            cp16ca(&sk[buf][tid * 4], g_kxW + base + (size_t)tid * 4);
            cp16ca(&sx[buf][tid * 4], g_xW1 + base + (size_t)tid * 4);
            if (tid == 0) cp16ca(sks[buf], g_kscore + ((size_t)b * 512 + t + 2) * 4);
        }
        asm volatile("cp.async.commit_group;" ::: "memory");

        if (tid < 4) {
            float s = c2;
#pragma unroll
            for (int ww = 0; ww < 8; ww++) s += wp[ww][tid];
            qs[tid] = s;
        }
    }
}

// ---------------- epilogue ----------------
__global__ void k_hfinal(const float* __restrict__ W2, const float* __restrict__ b2,
                         float* __restrict__ out) {
    int r = blockIdx.x, tid = threadIdx.x;
    __shared__ float sh[256];
    sh[tid] = g_h1[r * 256 + tid];
    __syncthreads();
    float acc = b2[tid];
    for (int h = 0; h < 256; h++) acc += sh[h] * W2[h * 256 + tid];
    g_hidden[r * 256 + tid] = acc;
    out[192 + r * 256 + tid] = acc;
}

__global__ void k_logits(const float* __restrict__ Wo, const float* __restrict__ bo,
                         float* __restrict__ out) {
    int bidx = blockIdx.x, tid = threadIdx.x, lane = tid & 31, wid = tid >> 5;
    __shared__ float red[4][3];
    float p0 = 0.f, p1 = 0.f, p2 = 0.f;
    for (int k = tid; k < 1024; k += 128) {
        float h = g_hidden[bidx * 1024 + k];
        p0 += h * Wo[k * 3 + 0];
        p1 += h * Wo[k * 3 + 1];
        p2 += h * Wo[k * 3 + 2];
    }
#pragma unroll
    for (int off = 16; off; off >>= 1) {
        p0 += __shfl_down_sync(0xFFFFFFFFu, p0, off);
        p1 += __shfl_down_sync(0xFFFFFFFFu, p1, off);
        p2 += __shfl_down_sync(0xFFFFFFFFu, p2, off);
    }
    if (lane == 0) { red[wid][0] = p0; red[wid][1] = p1; red[wid][2] = p2; }
    __syncthreads();
    if (tid == 0) {
        float l0 = bo[0], l1 = bo[1], l2 = bo[2];
        for (int w = 0; w < 4; w++) { l0 += red[w][0]; l1 += red[w][1]; l2 += red[w][2]; }
        float m = fmaxf(l0, fmaxf(l1, l2));
        float lse = m + logf(expf(l0 - m) + expf(l1 - m) + expf(l2 - m));
        out[bidx * 3 + 0] = l0 - lse;
        out[bidx * 3 + 1] = l1 - lse;
        out[bidx * 3 + 2] = l2 - lse;
    }
}

// ---------------- launch ----------------
extern "C" void kernel_launch(void* const* d_in, const int* in_sizes, int n_in,
                              void* d_out, int out_size) {
    const float* x     = (const float*)d_in[0];
    const float* Wk    = (const float*)d_in[1];
    const float* bk    = (const float*)d_in[2];
    const float* Wq    = (const float*)d_in[3];
    const float* bq    = (const float*)d_in[4];
    const float* w_mlp = (const float*)d_in[5];
    const float* Wproj = (const float*)d_in[6];
    const float* bproj = (const float*)d_in[7];
    const float* W1    = (const float*)d_in[8];
    const float* b1    = (const float*)d_in[9];
    const float* W2    = (const float*)d_in[10];
    const float* b2    = (const float*)d_in[11];
    const float* Wo    = (const float*)d_in[12];
    const float* bo    = (const float*)d_in[13];
    float* out = (float*)d_out;

    static bool attr_done = false;
    if (!attr_done) {
        cudaFuncSetAttribute(k_wmma, cudaFuncAttributeMaxDynamicSharedMemorySize, WSM_TOTAL);
        attr_done = true;
    }

    k_setup1<<<1, 256>>>(Wk, bk, Wq, bq, w_mlp);
    k_wcomb<<<256, 256>>>(Wproj, W1);
    k_wkc<<<257, 256>>>(Wk, W1, bk, b1, bproj, W2, b2);
    k_convA<<<16384, 256>>>(x);
    k_convB<<<512, 256>>>();
    k_wmma<<<dim3(4, 1024), 256, WSM_TOTAL>>>();
    k_recurrent<<<64, 256>>>();
    k_hfinal<<<256, 256>>>(W2, b2, out);
    k_logits<<<64, 128>>>(Wo, bo, out);
}